// round 5
// baseline (speedup 1.0000x reference)
#include <cuda_runtime.h>
#include <cuda_bf16.h>

#define NN    8000
#define NFEAT 512
#define NHID  128
#define NCLS  64
#define MAXNB 96
#define NIDX  500

// ---- scratch (static device globals; no runtime allocation) ----
__device__ float g_h[NN * NHID];        // h = relu(x@W0+b0) == h0
__device__ float g_yhat[NN * NCLS];
__device__ float g_liA[NN * NHID];
__device__ int   g_cols[NN * MAXNB];
__device__ float g_vals[NN * MAXNB];
__device__ int   g_nnz[NN];

// ===============================================================
// K1: heterogeneous front end.
//   blocks [0,1000):     adjacency ELL extraction (DRAM-bound, MLP=4)
//   blocks [1000,1250):  GEMM1 h = relu(x@W0+b0)  (FFMA-bound)
// ===============================================================
__device__ __forceinline__ void scan_group(float4 v, int base, int lane,
                                           unsigned below, int row, int& count) {
    bool any = (v.x != 0.f) | (v.y != 0.f) | (v.z != 0.f) | (v.w != 0.f);
    unsigned mg = __ballot_sync(~0u, any);
    if (mg == 0u) return;                 // fast path: whole 128-float group zero
    float e[4] = {v.x, v.y, v.z, v.w};
#pragma unroll
    for (int c = 0; c < 4; c++) {
        unsigned m = __ballot_sync(~0u, e[c] != 0.f);
        if (e[c] != 0.f) {
            int pos = count + __popc(m & below);
            if (pos < MAXNB) g_cols[row * MAXNB + pos] = base + lane * 4 + c;
        }
        count += __popc(m);
    }
}

__global__ void __launch_bounds__(256) k_front(const float* __restrict__ adj,
                                               const float* __restrict__ x,
                                               const float* __restrict__ W0,
                                               const float* __restrict__ b0) {
    __shared__ float As[16][64];
    __shared__ float Bs[16][64];

    if (blockIdx.x < 1000) {
        const int row  = blockIdx.x * 8 + (threadIdx.x >> 5);
        const int lane = threadIdx.x & 31;
        const float* arow = adj + (size_t)row * NN;
        const float4* arow4 = (const float4*)arow;
        int count = 0;
        const unsigned below = (1u << lane) - 1u;
        // 62 groups of 128 floats (7936) processed in batches of 4 (MLP=4)
        for (int b = 0; b < 15; b++) {
            float4 v[4];
#pragma unroll
            for (int u = 0; u < 4; u++)
                v[u] = __ldcs(&arow4[(b * 4 + u) * 32 + lane]);
#pragma unroll
            for (int u = 0; u < 4; u++)
                scan_group(v[u], (b * 4 + u) * 128, lane, below, row, count);
        }
        {   // groups 60,61
            float4 v0 = __ldcs(&arow4[60 * 32 + lane]);
            float4 v1 = __ldcs(&arow4[61 * 32 + lane]);
            scan_group(v0, 60 * 128, lane, below, row, count);
            scan_group(v1, 61 * 128, lane, below, row, count);
        }
        {   // tail: 64 floats at 7936
            float2 t = __ldcs(&((const float2*)(arow + 7936))[lane]);
            float e[2] = {t.x, t.y};
#pragma unroll
            for (int c = 0; c < 2; c++) {
                unsigned m = __ballot_sync(~0u, e[c] != 0.f);
                if (e[c] != 0.f) {
                    int pos = count + __popc(m & below);
                    if (pos < MAXNB) g_cols[row * MAXNB + pos] = 7936 + lane * 2 + c;
                }
                count += __popc(m);
            }
        }
        if (lane == 0) g_nnz[row] = count < MAXNB ? count : MAXNB;
    } else {
        // ---------- GEMM1: 64x64x16 tiles, 4x4 microtiles ----------
        const int bid  = blockIdx.x - 1000;
        const int bCol = bid / 125;
        const int bRow = bid % 125;
        const int tid  = threadIdx.x;
        const int tRow = tid >> 4;
        const int tCol = tid & 15;
        const int aRow = tid >> 2;
        const int aK   = (tid & 3) * 4;
        const int bK   = tid >> 4;
        const int bN   = (tid & 15) * 4;

        const float* Ag = x + (size_t)(bRow * 64 + aRow) * NFEAT;
        const float* Bg = W0 + bCol * 64;

        float acc[4][4];
#pragma unroll
        for (int i = 0; i < 4; i++)
#pragma unroll
            for (int j = 0; j < 4; j++) acc[i][j] = 0.f;

        for (int kt = 0; kt < NFEAT; kt += 16) {
            float4 av = *(const float4*)(Ag + kt + aK);
            As[aK + 0][aRow] = av.x;
            As[aK + 1][aRow] = av.y;
            As[aK + 2][aRow] = av.z;
            As[aK + 3][aRow] = av.w;
            float4 bv = *(const float4*)(Bg + (size_t)(kt + bK) * NHID + bN);
            *(float4*)&Bs[bK][bN] = bv;
            __syncthreads();
#pragma unroll
            for (int k = 0; k < 16; k++) {
                float rm[4], rn[4];
#pragma unroll
                for (int i = 0; i < 4; i++) rm[i] = As[k][tRow * 4 + i];
#pragma unroll
                for (int j = 0; j < 4; j++) rn[j] = Bs[k][tCol * 4 + j];
#pragma unroll
                for (int i = 0; i < 4; i++)
#pragma unroll
                    for (int j = 0; j < 4; j++) acc[i][j] += rm[i] * rn[j];
            }
            __syncthreads();
        }
#pragma unroll
        for (int i = 0; i < 4; i++) {
            int row = bRow * 64 + tRow * 4 + i;
#pragma unroll
            for (int j = 0; j < 4; j++) {
                int col = bCol * 64 + tCol * 4 + j;
                float v = acc[i][j] + b0[col];
                g_h[row * NHID + col] = v > 0.f ? v : 0.f;
            }
        }
    }
}

// ===============================================================
// K2: Pseudo = h@W1+b1 + 0.1*cnt(row)*y_label[row]; emit Pseudo;
//     y_hat = softmax(Pseudo).  (idx sorted -> binary-search count)
// ===============================================================
__global__ void __launch_bounds__(256) k_pseudo_fused(const float* __restrict__ W1,
                                                      const float* __restrict__ b1,
                                                      const int*   __restrict__ idx,
                                                      const float* __restrict__ ylab,
                                                      float* __restrict__ outPseudo) {
    __shared__ float Ws[NHID * NCLS];
    __shared__ float bs[NCLS];
    __shared__ float rowbuf[8][NHID];
    __shared__ int   s_idx[NIDX];
    const int tid = threadIdx.x;
    for (int i = tid; i < NHID * NCLS; i += 256) Ws[i] = W1[i];
    if (tid < NCLS) bs[tid] = b1[tid];
    for (int i = tid; i < NIDX; i += 256) s_idx[i] = idx[i];
    __syncthreads();

    const int warp = tid >> 5, lane = tid & 31;
    const int row  = blockIdx.x * 8 + warp;
    float4 v = *(const float4*)(g_h + (size_t)row * NHID + lane * 4);
    *(float4*)&rowbuf[warp][lane * 4] = v;
    __syncwarp();

    int lo = 0, hi = NIDX;
    while (lo < hi) { int mid = (lo + hi) >> 1; if (s_idx[mid] < row) lo = mid + 1; else hi = mid; }
    int lb = lo; hi = NIDX;
    while (lo < hi) { int mid = (lo + hi) >> 1; if (s_idx[mid] <= row) lo = mid + 1; else hi = mid; }
    const float cf = 0.1f * (float)(lo - lb);

    const int c0 = lane * 2, c1 = c0 + 1;
    float a0 = bs[c0], a1 = bs[c1];
#pragma unroll 8
    for (int k = 0; k < NHID; k++) {
        float hk = rowbuf[warp][k];
        float2 w = *(const float2*)&Ws[k * NCLS + c0];
        a0 += hk * w.x;
        a1 += hk * w.y;
    }
    if (cf != 0.f) {
        a0 += cf * ylab[row * NCLS + c0];
        a1 += cf * ylab[row * NCLS + c1];
    }
    float2 p; p.x = a0; p.y = a1;
    *(float2*)(outPseudo + row * NCLS + c0) = p;

    float m = fmaxf(a0, a1);
#pragma unroll
    for (int o = 16; o; o >>= 1) m = fmaxf(m, __shfl_xor_sync(~0u, m, o));
    float e0 = expf(a0 - m), e1 = expf(a1 - m);
    float s = e0 + e1;
#pragma unroll
    for (int o = 16; o; o >>= 1) s += __shfl_xor_sync(~0u, s, o);
    float inv = 1.f / s;
    float2 y; y.x = e0 * inv; y.y = e1 * inv;
    *(float2*)(g_yhat + row * NCLS + c0) = y;
}

// ---- unrolled gather: acc += sum_k w_k * src[c_k]  (MLP=4) ----
__device__ __forceinline__ float4 gather_spmm(const float* __restrict__ src,
                                              const int* cols, const float* vals,
                                              int nnz, int lane) {
    float4 a0 = make_float4(0, 0, 0, 0), a1 = a0, a2 = a0, a3 = a0;
    int k = 0;
    for (; k + 4 <= nnz; k += 4) {
        int   c0 = cols[k],     c1 = cols[k + 1], c2 = cols[k + 2], c3 = cols[k + 3];
        float w0 = vals[k],     w1 = vals[k + 1], w2 = vals[k + 2], w3 = vals[k + 3];
        float4 v0 = *(const float4*)(src + (size_t)c0 * NHID + lane * 4);
        float4 v1 = *(const float4*)(src + (size_t)c1 * NHID + lane * 4);
        float4 v2 = *(const float4*)(src + (size_t)c2 * NHID + lane * 4);
        float4 v3 = *(const float4*)(src + (size_t)c3 * NHID + lane * 4);
        a0.x += w0 * v0.x; a0.y += w0 * v0.y; a0.z += w0 * v0.z; a0.w += w0 * v0.w;
        a1.x += w1 * v1.x; a1.y += w1 * v1.y; a1.z += w1 * v1.z; a1.w += w1 * v1.w;
        a2.x += w2 * v2.x; a2.y += w2 * v2.y; a2.z += w2 * v2.z; a2.w += w2 * v2.w;
        a3.x += w3 * v3.x; a3.y += w3 * v3.y; a3.z += w3 * v3.z; a3.w += w3 * v3.w;
    }
    for (; k < nnz; k++) {
        int c = cols[k]; float w = vals[k];
        float4 v = *(const float4*)(src + (size_t)c * NHID + lane * 4);
        a0.x += w * v.x; a0.y += w * v.y; a0.z += w * v.z; a0.w += w * v.w;
    }
    a0.x += a1.x + a2.x + a3.x;
    a0.y += a1.y + a2.y + a3.y;
    a0.z += a1.z + a2.z + a3.z;
    a0.w += a1.w + a2.w + a3.w;
    return a0;
}

// ===============================================================
// K3: mask weights (lane-per-neighbor) + SpMM layer 0 + residual
//     + L2 norm -> liA.  Persists normalized vals for layer 1.
// ===============================================================
__global__ void __launch_bounds__(256) k_mask_spmm0() {
    __shared__ __align__(16) float vals_s[8][MAXNB];
    __shared__ int   cols_s[8][MAXNB];
    __shared__ __align__(16) float yi_s[8][NCLS];
    const int warp = threadIdx.x >> 5, lane = threadIdx.x & 31;
    const int row  = blockIdx.x * 8 + warp;
    const int nnz  = g_nnz[row];
    const int off  = row * MAXNB;
    for (int k = lane; k < nnz; k += 32) cols_s[warp][k] = g_cols[off + k];
    *(float2*)&yi_s[warp][lane * 2] = *(const float2*)(g_yhat + row * NCLS + lane * 2);
    __syncwarp();

    // lane-per-neighbor full 64-class dot (MLP=16, no per-edge shfl)
    for (int k0 = 0; k0 < nnz; k0 += 32) {
        int k = k0 + lane;
        float d = 0.f;
        if (k < nnz) {
            const float4* yj = (const float4*)(g_yhat + (size_t)cols_s[warp][k] * NCLS);
#pragma unroll
            for (int q = 0; q < 16; q++) {
                float4 a = yj[q];
                float4 b = *(const float4*)&yi_s[warp][q * 4];
                d += a.x * b.x + a.y * b.y + a.z * b.z + a.w * b.w;
            }
            vals_s[warp][k] = d;
        }
    }
    __syncwarp();
    float rsum = 0.f;
    for (int k = lane; k < nnz; k += 32) rsum += vals_s[warp][k];
#pragma unroll
    for (int o = 16; o; o >>= 1) rsum += __shfl_xor_sync(~0u, rsum, o);
    const float inv = 1.f / fmaxf(rsum, 1e-12f);
    for (int k = lane; k < nnz; k += 32) {
        float w = vals_s[warp][k] * inv;
        vals_s[warp][k] = w;
        g_vals[off + k] = w;
    }
    __syncwarp();

    float4 acc = gather_spmm(g_h, cols_s[warp], vals_s[warp], nnz, lane);
    float4 h0 = *(const float4*)(g_h + (size_t)row * NHID + lane * 4);
    float4 r;
    r.x = 0.9f * acc.x + 0.1f * h0.x;
    r.y = 0.9f * acc.y + 0.1f * h0.y;
    r.z = 0.9f * acc.z + 0.1f * h0.z;
    r.w = 0.9f * acc.w + 0.1f * h0.w;
    float ss = r.x * r.x + r.y * r.y + r.z * r.z + r.w * r.w;
#pragma unroll
    for (int o = 16; o; o >>= 1) ss += __shfl_xor_sync(~0u, ss, o);
    float ninv = 1.f / fmaxf(sqrtf(ss), 1e-12f);
    r.x *= ninv; r.y *= ninv; r.z *= ninv; r.w *= ninv;
    *(float4*)(g_liA + (size_t)row * NHID + lane * 4) = r;
}

// ===============================================================
// K4: SpMM layer 1 + residual + L2 norm, then
//     out = log_softmax(liB_row @ W2 + b2).
// ===============================================================
__global__ void __launch_bounds__(256) k_spmm1_out(const float* __restrict__ W2,
                                                   const float* __restrict__ b2,
                                                   float* __restrict__ out) {
    __shared__ float Ws[NHID * NCLS];
    __shared__ float bs[NCLS];
    __shared__ float rowbuf[8][NHID];
    __shared__ __align__(16) float vals_s[8][MAXNB];
    __shared__ int   cols_s[8][MAXNB];
    const int tid = threadIdx.x;
    for (int i = tid; i < NHID * NCLS; i += 256) Ws[i] = W2[i];
    if (tid < NCLS) bs[tid] = b2[tid];
    __syncthreads();

    const int warp = tid >> 5, lane = tid & 31;
    const int row  = blockIdx.x * 8 + warp;
    const int nnz  = g_nnz[row];
    const int off  = row * MAXNB;
    for (int k = lane; k < nnz; k += 32) {
        cols_s[warp][k] = g_cols[off + k];
        vals_s[warp][k] = g_vals[off + k];
    }
    __syncwarp();

    float4 acc = gather_spmm(g_liA, cols_s[warp], vals_s[warp], nnz, lane);
    float4 h0 = *(const float4*)(g_h + (size_t)row * NHID + lane * 4);
    float4 r;
    r.x = 0.9f * acc.x + 0.1f * h0.x;
    r.y = 0.9f * acc.y + 0.1f * h0.y;
    r.z = 0.9f * acc.z + 0.1f * h0.z;
    r.w = 0.9f * acc.w + 0.1f * h0.w;
    float ss = r.x * r.x + r.y * r.y + r.z * r.z + r.w * r.w;
#pragma unroll
    for (int o = 16; o; o >>= 1) ss += __shfl_xor_sync(~0u, ss, o);
    float ninv = 1.f / fmaxf(sqrtf(ss), 1e-12f);
    r.x *= ninv; r.y *= ninv; r.z *= ninv; r.w *= ninv;
    *(float4*)&rowbuf[warp][lane * 4] = r;
    __syncwarp();

    const int c0 = lane * 2, c1 = c0 + 1;
    float a0 = bs[c0], a1 = bs[c1];
#pragma unroll 8
    for (int k = 0; k < NHID; k++) {
        float hk = rowbuf[warp][k];
        float2 w = *(const float2*)&Ws[k * NCLS + c0];
        a0 += hk * w.x;
        a1 += hk * w.y;
    }
    float m = fmaxf(a0, a1);
#pragma unroll
    for (int o = 16; o; o >>= 1) m = fmaxf(m, __shfl_xor_sync(~0u, m, o));
    float e0 = expf(a0 - m), e1 = expf(a1 - m);
    float s = e0 + e1;
#pragma unroll
    for (int o = 16; o; o >>= 1) s += __shfl_xor_sync(~0u, s, o);
    float ls = logf(s);
    out[row * NCLS + c0] = a0 - m - ls;
    out[row * NCLS + c1] = a1 - m - ls;
}

extern "C" void kernel_launch(void* const* d_in, const int* in_sizes, int n_in,
                              void* d_out, int out_size) {
    const float* x    = (const float*)d_in[0];
    const float* adj  = (const float*)d_in[1];
    const float* ylab = (const float*)d_in[2];
    const int*   idx  = (const int*)  d_in[3];
    const float* W0   = (const float*)d_in[4];
    const float* b0   = (const float*)d_in[5];
    const float* W1   = (const float*)d_in[6];
    const float* b1   = (const float*)d_in[7];
    const float* W2   = (const float*)d_in[8];
    const float* b2   = (const float*)d_in[9];
    float* out = (float*)d_out;                  // [log_softmax | Pseudo]

    k_front<<<1250, 256>>>(adj, x, W0, b0);
    k_pseudo_fused<<<1000, 256>>>(W1, b1, idx, ylab, out + NN * NCLS);
    k_mask_spmm0<<<1000, 256>>>();
    k_spmm1_out<<<1000, 256>>>(W2, b2, out);
}

// round 6
// speedup vs baseline: 1.4492x; 1.4492x over previous
#include <cuda_runtime.h>
#include <cuda_bf16.h>

#define NN    8000
#define NFEAT 512
#define NHID  128
#define NCLS  64
#define MAXNB 96
#define NIDX  500
#define NGEMMB 125

// ---- scratch (static device globals; no runtime allocation) ----
__device__ float g_h[NN * NHID];        // h = relu(x@W0+b0) == h0
__device__ float g_yhat[NN * NCLS];
__device__ float g_liA[NN * NHID];
__device__ int   g_cols[NN * MAXNB];
__device__ float g_vals[NN * MAXNB];
__device__ int   g_nnz[NN];

// ===============================================================
// K1: heterogeneous front end.
//   blocks [0,125):     GEMM1 64x128 tile + Pseudo + inject + softmax
//   blocks [125,1125):  adjacency ELL extraction (DRAM-bound)
// ===============================================================
__device__ __forceinline__ void scan_group(float4 v, int base, int lane,
                                           unsigned below, int row, int& count) {
    bool any = (v.x != 0.f) | (v.y != 0.f) | (v.z != 0.f) | (v.w != 0.f);
    unsigned mg = __ballot_sync(~0u, any);
    if (mg == 0u) return;                 // whole 128-float group zero
    float e[4] = {v.x, v.y, v.z, v.w};
#pragma unroll
    for (int c = 0; c < 4; c++) {
        unsigned m = __ballot_sync(~0u, e[c] != 0.f);
        if (e[c] != 0.f) {
            int pos = count + __popc(m & below);
            if (pos < MAXNB) g_cols[row * MAXNB + pos] = base + lane * 4 + c;
        }
        count += __popc(m);
    }
}

__global__ void __launch_bounds__(256) k_front(const float* __restrict__ adj,
                                               const float* __restrict__ x,
                                               const float* __restrict__ W0,
                                               const float* __restrict__ b0,
                                               const float* __restrict__ W1,
                                               const float* __restrict__ b1,
                                               const int*   __restrict__ idx,
                                               const float* __restrict__ ylab,
                                               float* __restrict__ outPseudo) {
    __shared__ float As[16][64];          // 4 KB
    __shared__ float Bs[16][128];         // 8 KB
    __shared__ float rowbuf[8][NHID];     // 4 KB
    __shared__ int   s_idx[NIDX];         // 2 KB

    const int tid  = threadIdx.x;
    const int warp = tid >> 5, lane = tid & 31;

    if (blockIdx.x >= NGEMMB) {
        // ---------- adjacency scan: warp per row, pairs of loads ----------
        const int row  = (blockIdx.x - NGEMMB) * 8 + warp;
        const float* arow = adj + (size_t)row * NN;
        const float4* arow4 = (const float4*)arow;
        int count = 0;
        const unsigned below = (1u << lane) - 1u;
        // 62 groups of 128 floats (7936), two loads in flight per iter
        for (int g = 0; g < 62; g += 2) {
            float4 v0 = arow4[g * 32 + lane];
            float4 v1 = arow4[(g + 1) * 32 + lane];
            scan_group(v0, g * 128, lane, below, row, count);
            scan_group(v1, (g + 1) * 128, lane, below, row, count);
        }
        {   // tail: 64 floats at 7936
            float2 t = ((const float2*)(arow + 7936))[lane];
            float e[2] = {t.x, t.y};
#pragma unroll
            for (int c = 0; c < 2; c++) {
                unsigned m = __ballot_sync(~0u, e[c] != 0.f);
                if (e[c] != 0.f) {
                    int pos = count + __popc(m & below);
                    if (pos < MAXNB) g_cols[row * MAXNB + pos] = 7936 + lane * 2 + c;
                }
                count += __popc(m);
            }
        }
        if (lane == 0) g_nnz[row] = count < MAXNB ? count : MAXNB;
        return;
    }

    // ---------- GEMM1: 64 rows x 128 cols, K=512, 4x8 microtiles ----------
    const int bRow = blockIdx.x;              // 0..124
    const int tRow = tid >> 4;                // 0..15 -> 4 rows each
    const int tCol = tid & 15;                // 0..15 -> 8 cols each
    const int aRow = tid >> 2;                // 0..63
    const int aK   = (tid & 3) * 4;           // 0,4,8,12
    const int bK   = tid >> 5;                // 0..7 (two k's: bK, bK+8)
    const int bN   = (tid & 31) * 4;          // 0..124

    for (int i = tid; i < NIDX; i += 256) s_idx[i] = idx[i];

    const float* Ag = x + (size_t)(bRow * 64 + aRow) * NFEAT;

    float acc[4][8];
#pragma unroll
    for (int i = 0; i < 4; i++)
#pragma unroll
        for (int j = 0; j < 8; j++) acc[i][j] = 0.f;

    for (int kt = 0; kt < NFEAT; kt += 16) {
        float4 av = *(const float4*)(Ag + kt + aK);
        float4 bv0 = *(const float4*)(W0 + (size_t)(kt + bK) * NHID + bN);
        float4 bv1 = *(const float4*)(W0 + (size_t)(kt + bK + 8) * NHID + bN);
        __syncthreads();   // protect previous iter's reads (and pseudo rowbuf reuse)
        As[aK + 0][aRow] = av.x;
        As[aK + 1][aRow] = av.y;
        As[aK + 2][aRow] = av.z;
        As[aK + 3][aRow] = av.w;
        *(float4*)&Bs[bK][bN]     = bv0;
        *(float4*)&Bs[bK + 8][bN] = bv1;
        __syncthreads();
#pragma unroll
        for (int k = 0; k < 16; k++) {
            float4 rm = *(const float4*)&As[k][tRow * 4];
            float4 rn0 = *(const float4*)&Bs[k][tCol * 8];
            float4 rn1 = *(const float4*)&Bs[k][tCol * 8 + 4];
            float m[4] = {rm.x, rm.y, rm.z, rm.w};
            float n[8] = {rn0.x, rn0.y, rn0.z, rn0.w, rn1.x, rn1.y, rn1.z, rn1.w};
#pragma unroll
            for (int i = 0; i < 4; i++)
#pragma unroll
                for (int j = 0; j < 8; j++) acc[i][j] += m[i] * n[j];
        }
    }
    // epilogue: bias + relu + store h
#pragma unroll
    for (int i = 0; i < 4; i++) {
        int row = bRow * 64 + tRow * 4 + i;
        float4 o0, o1;
        o0.x = acc[i][0] + b0[tCol * 8 + 0];
        o0.y = acc[i][1] + b0[tCol * 8 + 1];
        o0.z = acc[i][2] + b0[tCol * 8 + 2];
        o0.w = acc[i][3] + b0[tCol * 8 + 3];
        o1.x = acc[i][4] + b0[tCol * 8 + 4];
        o1.y = acc[i][5] + b0[tCol * 8 + 5];
        o1.z = acc[i][6] + b0[tCol * 8 + 6];
        o1.w = acc[i][7] + b0[tCol * 8 + 7];
        o0.x = o0.x > 0.f ? o0.x : 0.f;  o0.y = o0.y > 0.f ? o0.y : 0.f;
        o0.z = o0.z > 0.f ? o0.z : 0.f;  o0.w = o0.w > 0.f ? o0.w : 0.f;
        o1.x = o1.x > 0.f ? o1.x : 0.f;  o1.y = o1.y > 0.f ? o1.y : 0.f;
        o1.z = o1.z > 0.f ? o1.z : 0.f;  o1.w = o1.w > 0.f ? o1.w : 0.f;
        *(float4*)(g_h + (size_t)row * NHID + tCol * 8)     = o0;
        *(float4*)(g_h + (size_t)row * NHID + tCol * 8 + 4) = o1;
    }
    __syncthreads();   // block's g_h writes visible block-wide

    // ---------- Pseudo + inject + softmax for this block's 64 rows ----------
    // warp w handles rows  bRow*64 + w*8 + rr,  rr = 0..7
    for (int rr = 0; rr < 8; rr++) {
        const int row = bRow * 64 + warp * 8 + rr;
        float4 hv = *(const float4*)(g_h + (size_t)row * NHID + lane * 4); // L1 hit
        *(float4*)&rowbuf[warp][lane * 4] = hv;
        __syncwarp();

        // count of row in sorted idx
        int lo = 0, hi = NIDX;
        while (lo < hi) { int mid = (lo + hi) >> 1; if (s_idx[mid] < row) lo = mid + 1; else hi = mid; }
        int lb = lo; hi = NIDX;
        while (lo < hi) { int mid = (lo + hi) >> 1; if (s_idx[mid] <= row) lo = mid + 1; else hi = mid; }
        const float cf = 0.1f * (float)(lo - lb);

        const int c0 = lane * 2, c1 = c0 + 1;
        float a0 = b1[c0], a1 = b1[c1];
#pragma unroll 8
        for (int k = 0; k < NHID; k++) {
            float hk = rowbuf[warp][k];
            float2 w = *(const float2*)(W1 + k * NCLS + c0);
            a0 += hk * w.x;
            a1 += hk * w.y;
        }
        if (cf != 0.f) {
            a0 += cf * ylab[row * NCLS + c0];
            a1 += cf * ylab[row * NCLS + c1];
        }
        float2 p; p.x = a0; p.y = a1;
        *(float2*)(outPseudo + row * NCLS + c0) = p;

        float m = fmaxf(a0, a1);
#pragma unroll
        for (int o = 16; o; o >>= 1) m = fmaxf(m, __shfl_xor_sync(~0u, m, o));
        float e0 = expf(a0 - m), e1 = expf(a1 - m);
        float s = e0 + e1;
#pragma unroll
        for (int o = 16; o; o >>= 1) s += __shfl_xor_sync(~0u, s, o);
        float inv = 1.f / s;
        float2 y; y.x = e0 * inv; y.y = e1 * inv;
        *(float2*)(g_yhat + row * NCLS + c0) = y;
        __syncwarp();
    }
}

// ===============================================================
// K2: mask weights + SpMM layer 0 + residual + L2 norm -> liA.
//     (identical to the 170us round-4 version)
// ===============================================================
__global__ void __launch_bounds__(256) k_mask_spmm0() {
    __shared__ float vals_s[8][MAXNB];
    __shared__ int   cols_s[8][MAXNB];
    const int warp = threadIdx.x >> 5, lane = threadIdx.x & 31;
    const int row  = blockIdx.x * 8 + warp;
    const int nnz  = g_nnz[row];
    const int off  = row * MAXNB;
    for (int k = lane; k < nnz; k += 32) cols_s[warp][k] = g_cols[off + k];
    __syncwarp();

    float2 yi = *(const float2*)(g_yhat + row * NCLS + lane * 2);
    float rsum = 0.f;
    for (int k = 0; k < nnz; k++) {
        int c = cols_s[warp][k];
        float2 yj = *(const float2*)(g_yhat + c * NCLS + lane * 2);
        float d = yi.x * yj.x + yi.y * yj.y;
#pragma unroll
        for (int o = 16; o; o >>= 1) d += __shfl_xor_sync(~0u, d, o);
        if (lane == 0) vals_s[warp][k] = d;
        rsum += d;
    }
    __syncwarp();
    const float inv = 1.f / fmaxf(rsum, 1e-12f);
    for (int k = lane; k < nnz; k += 32) g_vals[off + k] = vals_s[warp][k] * inv;
    __syncwarp();

    float4 acc = make_float4(0.f, 0.f, 0.f, 0.f);
    for (int k = 0; k < nnz; k++) {
        int   c = cols_s[warp][k];
        float w = vals_s[warp][k] * inv;
        float4 v = *(const float4*)(g_h + (size_t)c * NHID + lane * 4);
        acc.x += w * v.x; acc.y += w * v.y; acc.z += w * v.z; acc.w += w * v.w;
    }
    float4 h0 = *(const float4*)(g_h + (size_t)row * NHID + lane * 4);
    float4 r;
    r.x = 0.9f * acc.x + 0.1f * h0.x;
    r.y = 0.9f * acc.y + 0.1f * h0.y;
    r.z = 0.9f * acc.z + 0.1f * h0.z;
    r.w = 0.9f * acc.w + 0.1f * h0.w;
    float ss = r.x * r.x + r.y * r.y + r.z * r.z + r.w * r.w;
#pragma unroll
    for (int o = 16; o; o >>= 1) ss += __shfl_xor_sync(~0u, ss, o);
    float ninv = 1.f / fmaxf(sqrtf(ss), 1e-12f);
    r.x *= ninv; r.y *= ninv; r.z *= ninv; r.w *= ninv;
    *(float4*)(g_liA + (size_t)row * NHID + lane * 4) = r;
}

// ===============================================================
// K3: SpMM layer 1 + residual + L2 norm, then
//     out = log_softmax(liB_row @ W2 + b2).
//     (identical to the 170us round-4 version)
// ===============================================================
__global__ void __launch_bounds__(256) k_spmm1_out(const float* __restrict__ W2,
                                                   const float* __restrict__ b2,
                                                   float* __restrict__ out) {
    __shared__ float Ws[NHID * NCLS];
    __shared__ float bs[NCLS];
    __shared__ float rowbuf[8][NHID];
    const int tid = threadIdx.x;
    for (int i = tid; i < NHID * NCLS; i += 256) Ws[i] = W2[i];
    if (tid < NCLS) bs[tid] = b2[tid];
    __syncthreads();

    const int warp = tid >> 5, lane = tid & 31;
    const int row  = blockIdx.x * 8 + warp;
    const int nnz  = g_nnz[row];
    const int off  = row * MAXNB;

    float4 acc = make_float4(0.f, 0.f, 0.f, 0.f);
    for (int k = 0; k < nnz; k++) {
        int   c = g_cols[off + k];
        float w = g_vals[off + k];
        float4 v = *(const float4*)(g_liA + (size_t)c * NHID + lane * 4);
        acc.x += w * v.x; acc.y += w * v.y; acc.z += w * v.z; acc.w += w * v.w;
    }
    float4 h0 = *(const float4*)(g_h + (size_t)row * NHID + lane * 4);
    float4 r;
    r.x = 0.9f * acc.x + 0.1f * h0.x;
    r.y = 0.9f * acc.y + 0.1f * h0.y;
    r.z = 0.9f * acc.z + 0.1f * h0.z;
    r.w = 0.9f * acc.w + 0.1f * h0.w;
    float ss = r.x * r.x + r.y * r.y + r.z * r.z + r.w * r.w;
#pragma unroll
    for (int o = 16; o; o >>= 1) ss += __shfl_xor_sync(~0u, ss, o);
    float ninv = 1.f / fmaxf(sqrtf(ss), 1e-12f);
    r.x *= ninv; r.y *= ninv; r.z *= ninv; r.w *= ninv;
    *(float4*)&rowbuf[warp][lane * 4] = r;
    __syncwarp();

    const int c0 = lane * 2, c1 = c0 + 1;
    float a0 = bs[c0], a1 = bs[c1];
#pragma unroll 8
    for (int k = 0; k < NHID; k++) {
        float hk = rowbuf[warp][k];
        float2 w = *(const float2*)&Ws[k * NCLS + c0];
        a0 += hk * w.x;
        a1 += hk * w.y;
    }
    float m = fmaxf(a0, a1);
#pragma unroll
    for (int o = 16; o; o >>= 1) m = fmaxf(m, __shfl_xor_sync(~0u, m, o));
    float e0 = expf(a0 - m), e1 = expf(a1 - m);
    float s = e0 + e1;
#pragma unroll
    for (int o = 16; o; o >>= 1) s += __shfl_xor_sync(~0u, s, o);
    float ls = logf(s);
    out[row * NCLS + c0] = a0 - m - ls;
    out[row * NCLS + c1] = a1 - m - ls;
}

extern "C" void kernel_launch(void* const* d_in, const int* in_sizes, int n_in,
                              void* d_out, int out_size) {
    const float* x    = (const float*)d_in[0];
    const float* adj  = (const float*)d_in[1];
    const float* ylab = (const float*)d_in[2];
    const int*   idx  = (const int*)  d_in[3];
    const float* W0   = (const float*)d_in[4];
    const float* b0   = (const float*)d_in[5];
    const float* W1   = (const float*)d_in[6];
    const float* b1   = (const float*)d_in[7];
    const float* W2   = (const float*)d_in[8];
    const float* b2   = (const float*)d_in[9];
    float* out = (float*)d_out;                  // [log_softmax | Pseudo]

    k_front<<<1125, 256>>>(adj, x, W0, b0, W1, b1, idx, ylab, out + NN * NCLS);
    k_mask_spmm0<<<1000, 256>>>();
    k_spmm1_out<<<1000, 256>>>(W2, b2, out);
}